// round 16
// baseline (speedup 1.0000x reference)
#include <cuda_runtime.h>
#include <cuda_fp16.h>
#include <cstdint>

// ---------------- problem constants ----------------
#define BB   64
#define TT   512
#define BT   (BB*TT)          // 32768
#define SKD  256
#define AND_ 96
#define DD   352              // SK+AN
#define HH   256
#define G4   1024             // 4*H
#define ATTD 80
#define NC   2000
#define RES_ELEMS ((size_t)BT*NC)    // 65,536,000
#define SAE_ELEMS ((size_t)BT*DD)    // 11,534,336

typedef unsigned long long u64;

// ---------------- device scratch (static, allowed) ----------------
__device__ __half g_sae_h  [BT*DD];        // 23 MB  (fp16 GEMM A)
__device__ float  g_xg     [BT*G4];        // 134 MB (fp32)
__device__ __half g_hall_h [BT*HH];        // 16.8 MB
__device__ float  g_scores [BT];
__device__ __half g_cum1_h [BT*HH];        // 16.8 MB (exclusive cumsum of attn)
// fp16 weight copies
__device__ __half g_wih_h [G4*DD];
__device__ __half g_mlpw_h[ATTD*HH];
__device__ __half g_fcw_h [NC*2*HH];

extern __shared__ float dynsmem[];

// ---------------- helpers ----------------
__device__ __forceinline__ float sigf(float x){ return 1.f/(1.f+__expf(-x)); }
__device__ __forceinline__ float tanhapx(float x){
    float y; asm("tanh.approx.f32 %0, %1;" : "=f"(y) : "f"(x)); return y;
}
__device__ __forceinline__ void ffma2(u64& d, u64 a, u64 b){
    asm volatile("fma.rn.f32x2 %0, %1, %2, %0;" : "+l"(d) : "l"(a), "l"(b));
}
__device__ __forceinline__ float hsum2(u64 v){
    float2 f = *reinterpret_cast<float2*>(&v); return f.x + f.y;
}
__device__ __forceinline__ void cpa16(uint32_t s, const void* g){
    asm volatile("cp.async.cg.shared.global [%0], [%1], 16;\n" :: "r"(s), "l"(g));
}
__device__ __forceinline__ void cpa16z(uint32_t s, const void* g, int ok){
    int bytes = ok ? 16 : 0;
    asm volatile("cp.async.cg.shared.global [%0], [%1], 16, %2;\n"
                 :: "r"(s), "l"(g), "r"(bytes));
}
__device__ __forceinline__ uint32_t smem_u32(const void* p){
    uint32_t a;
    asm("{ .reg .u64 t; cvta.to.shared.u64 t, %1; cvt.u32.u64 %0, t; }"
        : "=r"(a) : "l"(p));
    return a;
}
__device__ __forceinline__ void mb_wait_clu(uint32_t mb, int par){
    uint32_t done;
    asm volatile("{\n\t.reg .pred p;\n\t"
        "mbarrier.try_wait.parity.acquire.cluster.shared::cta.b64 p, [%1], %2;\n\t"
        "selp.b32 %0, 1, 0, p;\n\t}"
        : "=r"(done) : "r"(mb), "r"(par) : "memory");
    if (!done){
        asm volatile("{\n\t.reg .pred P1;\n\t"
            "W_%=:\n\t"
            "mbarrier.try_wait.parity.acquire.cluster.shared::cta.b64 P1, [%0], %1, 0x989680;\n\t"
            "@P1 bra.uni D_%=;\n\t"
            "bra.uni W_%=;\n\t"
            "D_%=:\n\t}"
            :: "r"(mb), "r"(par) : "memory");
    }
}

// ---------------- init: weights->fp16 ----------------
__global__ void atkt_init_all(const float* __restrict__ Wih,
                              const float* __restrict__ mlp_w,
                              const float* __restrict__ fc_w){
    int i = blockIdx.x*blockDim.x + threadIdx.x;
    if (i < G4*DD)    g_wih_h[i]  = __float2half_rn(Wih[i]);
    if (i < ATTD*HH)  g_mlpw_h[i] = __float2half_rn(mlp_w[i]);
    if (i < NC*2*HH)  g_fcw_h[i]  = __float2half_rn(fc_w[i]);
}

// ---------------- embedding gather + concat ----------------
__global__ void atkt_embed_kernel(const int* __restrict__ skill,
                                  const int* __restrict__ answer,
                                  const float* __restrict__ skill_emb,
                                  const float* __restrict__ answer_emb,
                                  float* __restrict__ out_sae){
    int bt = blockIdx.x;
    int d  = threadIdx.x;            // 0..351
    int ans = answer[bt];
    int sk  = skill[bt];
    float v;
    if (ans == 1) v = (d < SKD) ? skill_emb[sk*SKD + d]
                                : answer_emb[ans*AND_ + (d - SKD)];
    else          v = (d < AND_) ? answer_emb[ans*AND_ + d]
                                 : skill_emb[sk*SKD + (d - AND_)];
    size_t idx = (size_t)bt*DD + d;
    g_sae_h[idx] = __float2half_rn(v);   // GEMM operand
    if (out_sae) out_sae[idx] = v;       // exact output tail
}

// ================= fp16 mma GEMM (ldmatrix fragment loads) =================
#define HSTG 10240
__global__ __launch_bounds__(256, 2)
void atkt_gemm_h(const __half* __restrict__ A, int lda,
                 const __half* __restrict__ A2, int lda2, int K1,
                 const __half* __restrict__ Bm,
                 const float* __restrict__ bias1, const float* __restrict__ bias2,
                 const float* __restrict__ simw,
                 float* __restrict__ C, float* __restrict__ Cs,
                 int M, int N, int K, int act){
    __half* smh = (__half*)dynsmem;          // [3][HSTG] halves
    __shared__ float sc[128];
    const int tid  = threadIdx.x;
    const int lane = tid & 31, warp = tid >> 5;
    const int bm = blockIdx.y * 128, bn = blockIdx.x * 128;
    const int wm = (warp & 1) * 64, wn = (warp >> 1) * 32;
    const uint32_t sm0 = smem_u32(smh);

    float acc[4][4][4];
    #pragma unroll
    for (int i=0;i<4;i++)
      #pragma unroll
      for (int j=0;j<4;j++)
        #pragma unroll
        for (int q=0;q<4;q++) acc[i][j][q]=0.f;

    const int nkt = K >> 5;

    auto load_stage = [&](int s, int kt){
        int kb = kt << 5;
        const __half* Ap; int la, ko;
        if (K1 && kb >= K1){ Ap = A2; la = lda2; ko = kb - K1; }
        else               { Ap = A;  la = lda;  ko = kb; }
        #pragma unroll
        for (int i = 0; i < 2; ++i){
            int idx = tid + (i << 8);        // 0..511
            int row = idx >> 2;
            int c8  = (idx & 3) << 3;        // half col 0,8,16,24
            uint32_t so = sm0 + (uint32_t)s*(HSTG*2) + row*80 + (c8<<1);
            cpa16(so, Ap + (size_t)(bm + row)*la + ko + c8);
            int gn = bn + row;
            int gnc = (gn < N) ? gn : (N - 1);
            cpa16z(so + (HSTG), Bm + (size_t)gnc*K + kb + c8, gn < N);
        }
        asm volatile("cp.async.commit_group;\n");
    };

    const int a_rw = lane & 7;
    const int a_t  = lane >> 3;
    const int b_rw = lane & 7;
    const int b_t  = (lane >> 3) & 1;

    load_stage(0, 0);
    if (nkt > 1) load_stage(1, 1);
    for (int kt = 0; kt < nkt; ++kt){
        if (kt == nkt - 1) asm volatile("cp.async.wait_group 0;\n");
        else               asm volatile("cp.async.wait_group 1;\n");
        __syncthreads();
        if (kt + 2 < nkt) load_stage((kt + 2) % 3, kt + 2);
        const int s = kt % 3;
        const uint32_t sA = sm0 + (uint32_t)s*(HSTG*2);
        const uint32_t sB = sA + HSTG;
        #pragma unroll
        for (int ks = 0; ks < 2; ++ks){
            uint32_t af[4][4], bf[4][2];
            #pragma unroll
            for (int ma=0; ma<4; ma++){
                int row = wm + ma*16 + a_rw + ((a_t & 1) << 3);
                uint32_t addr = sA + (uint32_t)row*80
                              + (uint32_t)((ks<<4) + ((a_t >> 1) << 3))*2;
                asm volatile(
                  "ldmatrix.sync.aligned.m8n8.x4.shared.b16 {%0,%1,%2,%3}, [%4];"
                  : "=r"(af[ma][0]), "=r"(af[ma][1]),
                    "=r"(af[ma][2]), "=r"(af[ma][3])
                  : "r"(addr));
            }
            #pragma unroll
            for (int na=0; na<4; na++){
                int row = wn + na*8 + b_rw;
                uint32_t addr = sB + (uint32_t)row*80
                              + (uint32_t)((ks<<4) + (b_t << 3))*2;
                asm volatile(
                  "ldmatrix.sync.aligned.m8n8.x2.shared.b16 {%0,%1}, [%2];"
                  : "=r"(bf[na][0]), "=r"(bf[na][1])
                  : "r"(addr));
            }
            #pragma unroll
            for (int ma=0; ma<4; ma++)
                #pragma unroll
                for (int na=0; na<4; na++){
                    asm volatile(
                      "mma.sync.aligned.m16n8k16.row.col.f32.f16.f16.f32 "
                      "{%0,%1,%2,%3}, {%4,%5,%6,%7}, {%8,%9}, {%0,%1,%2,%3};\n"
                      : "+f"(acc[ma][na][0]), "+f"(acc[ma][na][1]),
                        "+f"(acc[ma][na][2]), "+f"(acc[ma][na][3])
                      : "r"(af[ma][0]), "r"(af[ma][1]), "r"(af[ma][2]), "r"(af[ma][3]),
                        "r"(bf[na][0]), "r"(bf[na][1]));
                }
        }
    }

    if (act == 3){
        if (tid < 128) sc[tid] = 0.f;
        __syncthreads();
        float part[4][2];
        #pragma unroll
        for (int ma=0; ma<4; ma++){ part[ma][0]=0.f; part[ma][1]=0.f; }
        #pragma unroll
        for (int ma=0; ma<4; ma++)
            #pragma unroll
            for (int na=0; na<4; na++)
                #pragma unroll
                for (int q=0; q<4; q++){
                    int cc = bn + wn + na*8 + (lane&3)*2 + (q&1);
                    if (cc < N){
                        float x = tanhf(acc[ma][na][q] + bias1[cc]);
                        part[ma][q>>1] += x * simw[cc];
                    }
                }
        #pragma unroll
        for (int ma=0; ma<4; ma++)
            #pragma unroll
            for (int qh=0; qh<2; qh++){
                float v = part[ma][qh];
                v += __shfl_xor_sync(0xffffffffu, v, 1);
                v += __shfl_xor_sync(0xffffffffu, v, 2);
                if ((lane & 3) == 0){
                    int rloc = wm + ma*16 + (lane>>2) + qh*8;
                    atomicAdd(&sc[rloc], v);
                }
            }
        __syncthreads();
        if (tid < 128) Cs[bm + tid] = sc[tid];
        return;
    }

    #pragma unroll
    for (int ma=0; ma<4; ma++){
        int row = bm + wm + ma*16 + (lane>>2);
        #pragma unroll
        for (int na=0; na<4; na++){
            int col = bn + wn + na*8 + (lane&3)*2;
            #pragma unroll
            for (int q=0;q<4;q++){
                int rr = row + ((q>=2) ? 8 : 0);
                int cc = col + (q&1);
                if (cc < N){
                    float x = acc[ma][na][q] + bias1[cc];
                    if (bias2) x += bias2[cc];
                    if (act==1)      x = sigf(x);
                    else if (act==2) x = tanhf(x);
                    C[(size_t)rr*N + cc] = x;
                }
            }
        }
    }
}
#define GEMM_SMEM (3*HSTG*2)   // 61440 bytes

// ---------------- cluster LSTM: 4-way batch-group software pipeline ---------
// 8 clusters x 8 CTAs x 256 threads. Each cluster owns 8 batches as FOUR
// interleaved groups of 2; group g's exchange latency is overlapped by the
// other THREE groups' compute. Register-resident fp32 Whh. Push-based DSMEM
// exchange; per-(group,buffer) mbarriers; wait deferred to just before use.
// smem floats: hsh[4 grp][2 buf][2 bb][256] @0 (4096)
//              red[2 bb][4 gate][8 kc][32 jl] @4096 (2048, groups sequential)
//              8 mbarriers @6144
#define LS_HSH  0
#define LS_RED  4096
#define MB_OFF  6144
#define LSTM_SMEM (6160*4)
__global__ __launch_bounds__(256, 1) __cluster_dims__(8,1,1)
void atkt_lstm_kernel(const float* __restrict__ Whh){
    float* sm = dynsmem;
    const int tid = threadIdx.x;
    uint32_t rank; asm("mov.u32 %0, %%cluster_ctarank;" : "=r"(rank)); // 0..7
    const int bg = blockIdx.x >> 3;               // cluster id 0..7 (8 batches)
    const int kc = tid >> 5;                      // k-chunk / warp id
    const int jl = tid & 31;                      // lane = local j

    u64 wreg[64];
    #pragma unroll
    for (int g = 0; g < 4; ++g){
        const float* src = Whh + ((size_t)((g<<8) + (int)rank*32 + jl))*256 + kc*32;
        #pragma unroll
        for (int k2 = 0; k2 < 16; ++k2)
            wreg[g*16 + k2] = *(const u64*)(src + k2*2);
    }
    for (int i = tid; i < 6144; i += 256) sm[i] = 0.f;
    const uint32_t smbase = smem_u32(sm);
    const uint32_t mb_local = smbase + MB_OFF*4;
    if (tid == 0){
        #pragma unroll
        for (int m = 0; m < 8; ++m)
            asm volatile("mbarrier.init.shared.b64 [%0], %1;"
                         :: "r"(mb_local + m*8), "r"(1024) : "memory");
    }
    __syncthreads();
    asm volatile("barrier.cluster.arrive.aligned;" ::: "memory");
    asm volatile("barrier.cluster.wait.aligned;"   ::: "memory");

    uint32_t rbase[8];
    #pragma unroll
    for (int r = 0; r < 8; ++r)
        asm volatile("mapa.shared::cluster.u32 %0, %1, %2;"
                     : "=r"(rbase[r]) : "r"(smbase), "r"(r));

    const int ebb = (tid >> 5) & 1;      // 0..1 for tid<64
    const int ej  = (int)rank*32 + jl;   // global j
    float c[4] = {0.f, 0.f, 0.f, 0.f};
    float nai[4], naf[4], nag[4], nao[4];
    if (tid < 64){
        #pragma unroll
        for (int g = 0; g < 4; ++g){
            int eb = bg*8 + g*2 + ebb;
            const float* xr0 = g_xg + (size_t)(eb*TT)*G4;
            nai[g] = xr0[ej]; naf[g] = xr0[256+ej];
            nag[g] = xr0[512+ej]; nao[g] = xr0[768+ej];
        }
    }

    int ph[4][2] = {{0,0},{0,0},{0,0},{0,0}};   // parity per (group, buffer)
    for (int t = 0; t < TT; ++t){
        const int cur = t & 1, nxt = cur ^ 1;
        #pragma unroll
        for (int g = 0; g < 4; ++g){
            // deferred wait: peers' h for this buffer must have landed
            if (t > 0){
                mb_wait_clu(mb_local + (uint32_t)(g*2 + cur)*8, ph[g][cur]);
                ph[g][cur] ^= 1;
            }
            // ---- compute partials: all 256 threads, 2 batches ----
            #pragma unroll
            for (int bb = 0; bb < 2; ++bb){
                const u64* hv = (const u64*)
                    &sm[LS_HSH + ((g*2 + cur)*2 + bb)*256 + kc*32];
                u64 p0=0, p1=0, p2=0, p3=0;
                #pragma unroll
                for (int k2 = 0; k2 < 16; ++k2){
                    u64 h2 = hv[k2];
                    ffma2(p0, h2, wreg[ 0 + k2]);
                    ffma2(p1, h2, wreg[16 + k2]);
                    ffma2(p2, h2, wreg[32 + k2]);
                    ffma2(p3, h2, wreg[48 + k2]);
                }
                float* rd = &sm[LS_RED + ((bb*4 + 0)*8 + kc)*32 + jl];
                rd[0*8*32]  = hsum2(p0);
                rd[1*8*32]  = hsum2(p1);
                rd[2*8*32]  = hsum2(p2);
                rd[3*8*32]  = hsum2(p3);
            }
            __syncthreads();   // partials ready; reads of hsh[g][cur] done
            // ---- reduction + gates + push: threads 0..63 ----
            if (tid < 64){
                float s0=0, s1=0, s2=0, s3=0;
                #pragma unroll
                for (int k = 0; k < 8; ++k){
                    s0 += sm[LS_RED + ((ebb*4 + 0)*8 + k)*32 + jl];
                    s1 += sm[LS_RED + ((ebb*4 + 1)*8 + k)*32 + jl];
                    s2 += sm[LS_RED + ((ebb*4 + 2)*8 + k)*32 + jl];
                    s3 += sm[LS_RED + ((ebb*4 + 3)*8 + k)*32 + jl];
                }
                float ai = nai[g] + s0, af = naf[g] + s1;
                float ag = nag[g] + s2, ao = nao[g] + s3;
                c[g] = sigf(af)*c[g] + sigf(ai)*tanhapx(ag);
                float h = sigf(ao)*tanhapx(c[g]);
                const int eb = bg*8 + g*2 + ebb;
                const int bt = eb*TT + t;
                g_hall_h[(size_t)bt*HH + ej] = __float2half_rn(h);
                if (t + 1 < TT){
                    const float* xr = g_xg + (size_t)(bt + 1)*G4;
                    nai[g] = __ldcg(xr + ej);
                    naf[g] = __ldcg(xr + 256 + ej);
                    nag[g] = __ldcg(xr + 512 + ej);
                    nao[g] = __ldcg(xr + 768 + ej);
                    uint32_t off =
                        (uint32_t)(LS_HSH + ((g*2 + nxt)*2 + ebb)*256 + ej)*4;
                    uint32_t hb = __float_as_uint(h);
                    #pragma unroll
                    for (int r = 0; r < 8; ++r)
                        asm volatile("st.shared::cluster.b32 [%0], %1;"
                                     :: "r"(rbase[r] + off), "r"(hb) : "memory");
                }
            }
            __syncthreads();   // pushes issued; red reusable by next group
            if (t + 1 < TT && tid < 8){
                asm volatile("fence.acq_rel.cluster;" ::: "memory");
                uint32_t ra = rbase[tid] + MB_OFF*4 + (uint32_t)(g*2 + nxt)*8;
                asm volatile(
                  "mbarrier.arrive.relaxed.cluster.shared::cluster.b64 _, [%0], %1;"
                  :: "r"(ra), "r"(128) : "memory");
            }
            // NOTE: no wait here — overlapped by the other 3 groups' compute
        }
    }
    asm volatile("barrier.cluster.arrive.aligned;" ::: "memory");
    asm volatile("barrier.cluster.wait.aligned;"   ::: "memory");
}

// ---------------- causal attention + exclusive cumsum -> g_cum1_h -----------
// 128 blocks = 64 batches x 2 halves of H; 8-deep load tiling (MLP=8).
__global__ void atkt_attn_kernel(){
    const int b   = blockIdx.x >> 1;
    const int j   = ((blockIdx.x & 1) << 7) + threadIdx.x;
    const int tid = threadIdx.x;
    __shared__ float e_sh[TT];
    __shared__ float red[128];
    float m = -1e30f;
    for (int t = tid; t < TT; t += 128) m = fmaxf(m, g_scores[b*TT + t]);
    red[tid] = m; __syncthreads();
    for (int s = 64; s; s >>= 1){
        if (tid < s) red[tid] = fmaxf(red[tid], red[tid+s]);
        __syncthreads();
    }
    float mm = red[0];
    for (int t = tid; t < TT; t += 128) e_sh[t] = __expf(g_scores[b*TT + t] - mm);
    __syncthreads();
    float num = 0.f, den = 0.f, acc2 = 0.f;
    const __half* hp = g_hall_h + (size_t)b*TT*HH + j;
    __half*      cp = g_cum1_h + (size_t)b*TT*HH + j;
    for (int tb = 0; tb < TT; tb += 8){
        __half hx[8];
        #pragma unroll
        for (int u = 0; u < 8; ++u)
            hx[u] = __ldcg(hp + (size_t)(tb + u)*HH);
        #pragma unroll
        for (int u = 0; u < 8; ++u){
            float hv = __half2float(hx[u]);
            float ev = e_sh[tb + u];
            den += ev; num += ev*hv;
            float attn = __fdividef(num, den);
            __stcg(cp + (size_t)(tb + u)*HH, __float2half_rn(acc2));
            acc2 += attn;
        }
    }
}

// ---------------- host launch ----------------
extern "C" void kernel_launch(void* const* d_in, const int* in_sizes, int n_in,
                              void* d_out, int out_size){
    const int*   skill      = (const int*)  d_in[0];
    const int*   answer     = (const int*)  d_in[1];
    const float* skill_emb  = (const float*)d_in[2];
    const float* answer_emb = (const float*)d_in[3];
    const float* Wih        = (const float*)d_in[4];
    const float* Whh        = (const float*)d_in[5];
    const float* bih        = (const float*)d_in[6];
    const float* bhh        = (const float*)d_in[7];
    const float* mlp_w      = (const float*)d_in[8];
    const float* mlp_b      = (const float*)d_in[9];
    const float* sim_w      = (const float*)d_in[10];
    const float* fc_w       = (const float*)d_in[11];
    const float* fc_b       = (const float*)d_in[12];
    float* out = (float*)d_out;

    __half *p_saeh, *p_hallh, *p_cum1h, *p_wihh, *p_mlpwh, *p_fcwh;
    float  *p_xg, *p_scores;
    cudaGetSymbolAddress((void**)&p_saeh,   g_sae_h);
    cudaGetSymbolAddress((void**)&p_xg,     g_xg);
    cudaGetSymbolAddress((void**)&p_hallh,  g_hall_h);
    cudaGetSymbolAddress((void**)&p_scores, g_scores);
    cudaGetSymbolAddress((void**)&p_cum1h,  g_cum1_h);
    cudaGetSymbolAddress((void**)&p_wihh,   g_wih_h);
    cudaGetSymbolAddress((void**)&p_mlpwh,  g_mlpw_h);
    cudaGetSymbolAddress((void**)&p_fcwh,   g_fcw_h);

    cudaFuncSetAttribute(atkt_lstm_kernel,
                         cudaFuncAttributeMaxDynamicSharedMemorySize, LSTM_SMEM);
    cudaFuncSetAttribute(atkt_gemm_h,
                         cudaFuncAttributeMaxDynamicSharedMemorySize, GEMM_SMEM);

    float* out_sae = ((size_t)out_size >= RES_ELEMS + SAE_ELEMS)
                     ? (out + RES_ELEMS) : nullptr;

    // 1) embeddings -> sae_h + exact tail of output
    atkt_embed_kernel<<<BT, DD>>>(skill, answer, skill_emb, answer_emb, out_sae);
    // 2) weights -> fp16
    atkt_init_all<<<(NC*2*HH + 255)/256, 256>>>(Wih, mlp_w, fc_w);
    // 3) xg = sae @ Wih^T + bih + bhh   [32768 x 1024]
    atkt_gemm_h<<<dim3(G4/128, BT/128), 256, GEMM_SMEM>>>(
        p_saeh, DD, nullptr, 0, 0, p_wihh, bih, bhh, nullptr,
        p_xg, nullptr, BT, G4, DD, 0);
    // 4) 4-way pipelined cluster LSTM scan -> g_hall_h   (profiled slot)
    atkt_lstm_kernel<<<64, 256, LSTM_SMEM>>>(Whh);
    // 5) scores = tanh(h @ mlp_w^T + mlp_b) . sim_w   (fused)
    atkt_gemm_h<<<dim3(1, BT/128), 256, GEMM_SMEM>>>(
        p_hallh, HH, nullptr, 0, 0, p_mlpwh, mlp_b, nullptr, sim_w,
        nullptr, p_scores, BT, ATTD, HH, 3);
    // 6) causal attention cumulative ratios -> g_cum1_h
    atkt_attn_kernel<<<2*BB, 128>>>();
    // 7) res = sigmoid([cum1|h] @ fc_w^T + fc_b) -> d_out  (split-A GEMM)
    atkt_gemm_h<<<dim3((NC + 127)/128, BT/128), 256, GEMM_SMEM>>>(
        p_cum1h, HH, p_hallh, HH, 256, p_fcwh, fc_b, nullptr, nullptr,
        out, nullptr, BT, NC, 2*HH, 1);
}

// round 17
// speedup vs baseline: 1.5796x; 1.5796x over previous
#include <cuda_runtime.h>
#include <cuda_fp16.h>
#include <cstdint>

// ---------------- problem constants ----------------
#define BB   64
#define TT   512
#define BT   (BB*TT)          // 32768
#define SKD  256
#define AND_ 96
#define DD   352              // SK+AN
#define HH   256
#define G4   1024             // 4*H
#define ATTD 80
#define NC   2000
#define RES_ELEMS ((size_t)BT*NC)    // 65,536,000
#define SAE_ELEMS ((size_t)BT*DD)    // 11,534,336

typedef unsigned long long u64;

// ---------------- device scratch (static, allowed) ----------------
__device__ __half g_sae_h  [BT*DD];        // 23 MB  (fp16 GEMM A)
__device__ float  g_xg     [BT*G4];        // 134 MB (fp32)
__device__ __half g_hall_h [BT*HH];        // 16.8 MB
__device__ float  g_scores [BT];
__device__ __half g_cum1_h [BT*HH];        // 16.8 MB (exclusive cumsum of attn)
// fp16 weight copies
__device__ __half g_wih_h [G4*DD];
__device__ __half g_mlpw_h[ATTD*HH];
__device__ __half g_fcw_h [NC*2*HH];

extern __shared__ float dynsmem[];

// ---------------- helpers ----------------
__device__ __forceinline__ float sigf(float x){ return 1.f/(1.f+__expf(-x)); }
__device__ __forceinline__ float tanhapx(float x){
    float y; asm("tanh.approx.f32 %0, %1;" : "=f"(y) : "f"(x)); return y;
}
__device__ __forceinline__ void ffma2(u64& d, u64 a, u64 b){
    asm volatile("fma.rn.f32x2 %0, %1, %2, %0;" : "+l"(d) : "l"(a), "l"(b));
}
__device__ __forceinline__ float hsum2(u64 v){
    float2 f = *reinterpret_cast<float2*>(&v); return f.x + f.y;
}
__device__ __forceinline__ void cpa16(uint32_t s, const void* g){
    asm volatile("cp.async.cg.shared.global [%0], [%1], 16;\n" :: "r"(s), "l"(g));
}
__device__ __forceinline__ void cpa16z(uint32_t s, const void* g, int ok){
    int bytes = ok ? 16 : 0;
    asm volatile("cp.async.cg.shared.global [%0], [%1], 16, %2;\n"
                 :: "r"(s), "l"(g), "r"(bytes));
}
__device__ __forceinline__ uint32_t smem_u32(const void* p){
    uint32_t a;
    asm("{ .reg .u64 t; cvta.to.shared.u64 t, %1; cvt.u32.u64 %0, t; }"
        : "=r"(a) : "l"(p));
    return a;
}
__device__ __forceinline__ void mb_wait_clu(uint32_t mb, int par){
    uint32_t done;
    asm volatile("{\n\t.reg .pred p;\n\t"
        "mbarrier.try_wait.parity.acquire.cluster.shared::cta.b64 p, [%1], %2;\n\t"
        "selp.b32 %0, 1, 0, p;\n\t}"
        : "=r"(done) : "r"(mb), "r"(par) : "memory");
    if (!done){
        asm volatile("{\n\t.reg .pred P1;\n\t"
            "W_%=:\n\t"
            "mbarrier.try_wait.parity.acquire.cluster.shared::cta.b64 P1, [%0], %1, 0x989680;\n\t"
            "@P1 bra.uni D_%=;\n\t"
            "bra.uni W_%=;\n\t"
            "D_%=:\n\t}"
            :: "r"(mb), "r"(par) : "memory");
    }
}

// ---------------- init: weights->fp16 ----------------
__global__ void atkt_init_all(const float* __restrict__ Wih,
                              const float* __restrict__ mlp_w,
                              const float* __restrict__ fc_w){
    int i = blockIdx.x*blockDim.x + threadIdx.x;
    if (i < G4*DD)    g_wih_h[i]  = __float2half_rn(Wih[i]);
    if (i < ATTD*HH)  g_mlpw_h[i] = __float2half_rn(mlp_w[i]);
    if (i < NC*2*HH)  g_fcw_h[i]  = __float2half_rn(fc_w[i]);
}

// ---------------- embedding gather + concat ----------------
__global__ void atkt_embed_kernel(const int* __restrict__ skill,
                                  const int* __restrict__ answer,
                                  const float* __restrict__ skill_emb,
                                  const float* __restrict__ answer_emb,
                                  float* __restrict__ out_sae){
    int bt = blockIdx.x;
    int d  = threadIdx.x;            // 0..351
    int ans = answer[bt];
    int sk  = skill[bt];
    float v;
    if (ans == 1) v = (d < SKD) ? skill_emb[sk*SKD + d]
                                : answer_emb[ans*AND_ + (d - SKD)];
    else          v = (d < AND_) ? answer_emb[ans*AND_ + d]
                                 : skill_emb[sk*SKD + (d - AND_)];
    size_t idx = (size_t)bt*DD + d;
    g_sae_h[idx] = __float2half_rn(v);   // GEMM operand
    if (out_sae) out_sae[idx] = v;       // exact output tail
}

// ================= fp16 mma GEMM (ldmatrix fragment loads) =================
#define HSTG 10240
__global__ __launch_bounds__(256, 2)
void atkt_gemm_h(const __half* __restrict__ A, int lda,
                 const __half* __restrict__ A2, int lda2, int K1,
                 const __half* __restrict__ Bm,
                 const float* __restrict__ bias1, const float* __restrict__ bias2,
                 const float* __restrict__ simw,
                 float* __restrict__ C, float* __restrict__ Cs,
                 int M, int N, int K, int act){
    __half* smh = (__half*)dynsmem;          // [3][HSTG] halves
    __shared__ float sc[128];
    const int tid  = threadIdx.x;
    const int lane = tid & 31, warp = tid >> 5;
    const int bm = blockIdx.y * 128, bn = blockIdx.x * 128;
    const int wm = (warp & 1) * 64, wn = (warp >> 1) * 32;
    const uint32_t sm0 = smem_u32(smh);

    float acc[4][4][4];
    #pragma unroll
    for (int i=0;i<4;i++)
      #pragma unroll
      for (int j=0;j<4;j++)
        #pragma unroll
        for (int q=0;q<4;q++) acc[i][j][q]=0.f;

    const int nkt = K >> 5;

    auto load_stage = [&](int s, int kt){
        int kb = kt << 5;
        const __half* Ap; int la, ko;
        if (K1 && kb >= K1){ Ap = A2; la = lda2; ko = kb - K1; }
        else               { Ap = A;  la = lda;  ko = kb; }
        #pragma unroll
        for (int i = 0; i < 2; ++i){
            int idx = tid + (i << 8);        // 0..511
            int row = idx >> 2;
            int c8  = (idx & 3) << 3;        // half col 0,8,16,24
            uint32_t so = sm0 + (uint32_t)s*(HSTG*2) + row*80 + (c8<<1);
            cpa16(so, Ap + (size_t)(bm + row)*la + ko + c8);
            int gn = bn + row;
            int gnc = (gn < N) ? gn : (N - 1);
            cpa16z(so + (HSTG), Bm + (size_t)gnc*K + kb + c8, gn < N);
        }
        asm volatile("cp.async.commit_group;\n");
    };

    const int a_rw = lane & 7;
    const int a_t  = lane >> 3;
    const int b_rw = lane & 7;
    const int b_t  = (lane >> 3) & 1;

    load_stage(0, 0);
    if (nkt > 1) load_stage(1, 1);
    for (int kt = 0; kt < nkt; ++kt){
        if (kt == nkt - 1) asm volatile("cp.async.wait_group 0;\n");
        else               asm volatile("cp.async.wait_group 1;\n");
        __syncthreads();
        if (kt + 2 < nkt) load_stage((kt + 2) % 3, kt + 2);
        const int s = kt % 3;
        const uint32_t sA = sm0 + (uint32_t)s*(HSTG*2);
        const uint32_t sB = sA + HSTG;
        #pragma unroll
        for (int ks = 0; ks < 2; ++ks){
            uint32_t af[4][4], bf[4][2];
            #pragma unroll
            for (int ma=0; ma<4; ma++){
                int row = wm + ma*16 + a_rw + ((a_t & 1) << 3);
                uint32_t addr = sA + (uint32_t)row*80
                              + (uint32_t)((ks<<4) + ((a_t >> 1) << 3))*2;
                asm volatile(
                  "ldmatrix.sync.aligned.m8n8.x4.shared.b16 {%0,%1,%2,%3}, [%4];"
                  : "=r"(af[ma][0]), "=r"(af[ma][1]),
                    "=r"(af[ma][2]), "=r"(af[ma][3])
                  : "r"(addr));
            }
            #pragma unroll
            for (int na=0; na<4; na++){
                int row = wn + na*8 + b_rw;
                uint32_t addr = sB + (uint32_t)row*80
                              + (uint32_t)((ks<<4) + (b_t << 3))*2;
                asm volatile(
                  "ldmatrix.sync.aligned.m8n8.x2.shared.b16 {%0,%1}, [%2];"
                  : "=r"(bf[na][0]), "=r"(bf[na][1])
                  : "r"(addr));
            }
            #pragma unroll
            for (int ma=0; ma<4; ma++)
                #pragma unroll
                for (int na=0; na<4; na++){
                    asm volatile(
                      "mma.sync.aligned.m16n8k16.row.col.f32.f16.f16.f32 "
                      "{%0,%1,%2,%3}, {%4,%5,%6,%7}, {%8,%9}, {%0,%1,%2,%3};\n"
                      : "+f"(acc[ma][na][0]), "+f"(acc[ma][na][1]),
                        "+f"(acc[ma][na][2]), "+f"(acc[ma][na][3])
                      : "r"(af[ma][0]), "r"(af[ma][1]), "r"(af[ma][2]), "r"(af[ma][3]),
                        "r"(bf[na][0]), "r"(bf[na][1]));
                }
        }
    }

    if (act == 3){
        if (tid < 128) sc[tid] = 0.f;
        __syncthreads();
        float part[4][2];
        #pragma unroll
        for (int ma=0; ma<4; ma++){ part[ma][0]=0.f; part[ma][1]=0.f; }
        #pragma unroll
        for (int ma=0; ma<4; ma++)
            #pragma unroll
            for (int na=0; na<4; na++)
                #pragma unroll
                for (int q=0; q<4; q++){
                    int cc = bn + wn + na*8 + (lane&3)*2 + (q&1);
                    if (cc < N){
                        float x = tanhf(acc[ma][na][q] + bias1[cc]);
                        part[ma][q>>1] += x * simw[cc];
                    }
                }
        #pragma unroll
        for (int ma=0; ma<4; ma++)
            #pragma unroll
            for (int qh=0; qh<2; qh++){
                float v = part[ma][qh];
                v += __shfl_xor_sync(0xffffffffu, v, 1);
                v += __shfl_xor_sync(0xffffffffu, v, 2);
                if ((lane & 3) == 0){
                    int rloc = wm + ma*16 + (lane>>2) + qh*8;
                    atomicAdd(&sc[rloc], v);
                }
            }
        __syncthreads();
        if (tid < 128) Cs[bm + tid] = sc[tid];
        return;
    }

    #pragma unroll
    for (int ma=0; ma<4; ma++){
        int row = bm + wm + ma*16 + (lane>>2);
        #pragma unroll
        for (int na=0; na<4; na++){
            int col = bn + wn + na*8 + (lane&3)*2;
            #pragma unroll
            for (int q=0;q<4;q++){
                int rr = row + ((q>=2) ? 8 : 0);
                int cc = col + (q&1);
                if (cc < N){
                    float x = acc[ma][na][q] + bias1[cc];
                    if (bias2) x += bias2[cc];
                    if (act==1)      x = sigf(x);
                    else if (act==2) x = tanhf(x);
                    C[(size_t)rr*N + cc] = x;
                }
            }
        }
    }
}
#define GEMM_SMEM (3*HSTG*2)   // 61440 bytes

// ---------------- cluster LSTM: 2-way batch-group software pipeline ---------
// 8 clusters x 8 CTAs x 256 threads; 2 groups of 4 batches (R15 structure).
// CHANGE vs R15: no fence.acq_rel.cluster — the mbarrier arrive now carries
// RELEASE semantics (cumulative over the pre-arrive __syncthreads), which is
// sufficient ordering for the consumer's acquire-wait and does not stall the
// producer draining remote stores.
// smem floats: hsh[2 grp][2 buf][4][256] @0 (4096) | red[4][4][8][32] @4096
//              (2048... 4096, groups sequential) | 4 mbarriers @8192
#define LS_HSH  0
#define LS_RED  4096
#define MB_OFF  8192
#define LSTM_SMEM (8208*4)
__global__ __launch_bounds__(256, 1) __cluster_dims__(8,1,1)
void atkt_lstm_kernel(const float* __restrict__ Whh){
    float* sm = dynsmem;
    const int tid = threadIdx.x;
    uint32_t rank; asm("mov.u32 %0, %%cluster_ctarank;" : "=r"(rank)); // 0..7
    const int bg = blockIdx.x >> 3;               // cluster id 0..7 (8 batches)
    const int kc = tid >> 5;                      // k-chunk / warp id
    const int jl = tid & 31;                      // lane = local j

    u64 wreg[64];
    #pragma unroll
    for (int g = 0; g < 4; ++g){
        const float* src = Whh + ((size_t)((g<<8) + (int)rank*32 + jl))*256 + kc*32;
        #pragma unroll
        for (int k2 = 0; k2 < 16; ++k2)
            wreg[g*16 + k2] = *(const u64*)(src + k2*2);
    }
    for (int i = tid; i < 8192; i += 256) sm[i] = 0.f;
    const uint32_t smbase = smem_u32(sm);
    const uint32_t mb_local = smbase + MB_OFF*4;
    if (tid == 0){
        #pragma unroll
        for (int m = 0; m < 4; ++m)
            asm volatile("mbarrier.init.shared.b64 [%0], %1;"
                         :: "r"(mb_local + m*8), "r"(1024) : "memory");
    }
    __syncthreads();
    asm volatile("barrier.cluster.arrive.aligned;" ::: "memory");
    asm volatile("barrier.cluster.wait.aligned;"   ::: "memory");

    uint32_t rbase[8];
    #pragma unroll
    for (int r = 0; r < 8; ++r)
        asm volatile("mapa.shared::cluster.u32 %0, %1, %2;"
                     : "=r"(rbase[r]) : "r"(smbase), "r"(r));

    const int ebb = tid >> 5;            // 0..3 for tid<128
    const int ej  = (int)rank*32 + jl;   // global j
    float c[2] = {0.f, 0.f};
    float nai[2], naf[2], nag[2], nao[2];
    if (tid < 128){
        #pragma unroll
        for (int g = 0; g < 2; ++g){
            int eb = bg*8 + g*4 + ebb;
            const float* xr0 = g_xg + (size_t)(eb*TT)*G4;
            nai[g] = xr0[ej]; naf[g] = xr0[256+ej];
            nag[g] = xr0[512+ej]; nao[g] = xr0[768+ej];
        }
    }

    int ph[2][2] = {{0,0},{0,0}};        // parity per (group, buffer)
    for (int t = 0; t < TT; ++t){
        const int cur = t & 1, nxt = cur ^ 1;
        #pragma unroll
        for (int g = 0; g < 2; ++g){
            // deferred wait: peers' h for this buffer must have landed
            if (t > 0){
                mb_wait_clu(mb_local + (uint32_t)(g*2 + cur)*8, ph[g][cur]);
                ph[g][cur] ^= 1;
            }
            // ---- compute partials: all 256 threads ----
            #pragma unroll
            for (int bb = 0; bb < 4; ++bb){
                const u64* hv = (const u64*)
                    &sm[LS_HSH + ((g*2 + cur)*4 + bb)*256 + kc*32];
                u64 p0=0, p1=0, p2=0, p3=0;
                #pragma unroll
                for (int k2 = 0; k2 < 16; ++k2){
                    u64 h2 = hv[k2];
                    ffma2(p0, h2, wreg[ 0 + k2]);
                    ffma2(p1, h2, wreg[16 + k2]);
                    ffma2(p2, h2, wreg[32 + k2]);
                    ffma2(p3, h2, wreg[48 + k2]);
                }
                float* rd = &sm[LS_RED + ((bb*4 + 0)*8 + kc)*32 + jl];
                rd[0*8*32]  = hsum2(p0);
                rd[1*8*32]  = hsum2(p1);
                rd[2*8*32]  = hsum2(p2);
                rd[3*8*32]  = hsum2(p3);
            }
            __syncthreads();   // partials ready; reads of hsh[g][cur] done
            // ---- reduction + gates + push: threads 0..127 ----
            if (tid < 128){
                float s0=0, s1=0, s2=0, s3=0;
                #pragma unroll
                for (int k = 0; k < 8; ++k){
                    s0 += sm[LS_RED + ((ebb*4 + 0)*8 + k)*32 + jl];
                    s1 += sm[LS_RED + ((ebb*4 + 1)*8 + k)*32 + jl];
                    s2 += sm[LS_RED + ((ebb*4 + 2)*8 + k)*32 + jl];
                    s3 += sm[LS_RED + ((ebb*4 + 3)*8 + k)*32 + jl];
                }
                float ai = nai[g] + s0, af = naf[g] + s1;
                float ag = nag[g] + s2, ao = nao[g] + s3;
                c[g] = sigf(af)*c[g] + sigf(ai)*tanhapx(ag);
                float h = sigf(ao)*tanhapx(c[g]);
                const int eb = bg*8 + g*4 + ebb;
                const int bt = eb*TT + t;
                g_hall_h[(size_t)bt*HH + ej] = __float2half_rn(h);
                if (t + 1 < TT){
                    const float* xr = g_xg + (size_t)(bt + 1)*G4;
                    nai[g] = __ldcg(xr + ej);
                    naf[g] = __ldcg(xr + 256 + ej);
                    nag[g] = __ldcg(xr + 512 + ej);
                    nao[g] = __ldcg(xr + 768 + ej);
                    uint32_t off =
                        (uint32_t)(LS_HSH + ((g*2 + nxt)*4 + ebb)*256 + ej)*4;
                    uint32_t hb = __float_as_uint(h);
                    #pragma unroll
                    for (int r = 0; r < 8; ++r)
                        asm volatile("st.shared::cluster.b32 [%0], %1;"
                                     :: "r"(rbase[r] + off), "r"(hb) : "memory");
                }
            }
            __syncthreads();   // pushes HB the release-arrive (cumulativity)
            if (t + 1 < TT && tid < 8){
                uint32_t ra = rbase[tid] + MB_OFF*4 + (uint32_t)(g*2 + nxt)*8;
                asm volatile(
                  "mbarrier.arrive.release.cluster.shared::cluster.b64 _, [%0], %1;"
                  :: "r"(ra), "r"(128) : "memory");
            }
            // no wait here — overlapped by the other group's compute
        }
    }
    asm volatile("barrier.cluster.arrive.aligned;" ::: "memory");
    asm volatile("barrier.cluster.wait.aligned;"   ::: "memory");
}

// ---------------- causal attention + exclusive cumsum -> g_cum1_h -----------
// 128 blocks = 64 batches x 2 halves of H; 8-deep load tiling (MLP=8).
__global__ void atkt_attn_kernel(){
    const int b   = blockIdx.x >> 1;
    const int j   = ((blockIdx.x & 1) << 7) + threadIdx.x;
    const int tid = threadIdx.x;
    __shared__ float e_sh[TT];
    __shared__ float red[128];
    float m = -1e30f;
    for (int t = tid; t < TT; t += 128) m = fmaxf(m, g_scores[b*TT + t]);
    red[tid] = m; __syncthreads();
    for (int s = 64; s; s >>= 1){
        if (tid < s) red[tid] = fmaxf(red[tid], red[tid+s]);
        __syncthreads();
    }
    float mm = red[0];
    for (int t = tid; t < TT; t += 128) e_sh[t] = __expf(g_scores[b*TT + t] - mm);
    __syncthreads();
    float num = 0.f, den = 0.f, acc2 = 0.f;
    const __half* hp = g_hall_h + (size_t)b*TT*HH + j;
    __half*      cp = g_cum1_h + (size_t)b*TT*HH + j;
    for (int tb = 0; tb < TT; tb += 8){
        __half hx[8];
        #pragma unroll
        for (int u = 0; u < 8; ++u)
            hx[u] = __ldcg(hp + (size_t)(tb + u)*HH);
        #pragma unroll
        for (int u = 0; u < 8; ++u){
            float hv = __half2float(hx[u]);
            float ev = e_sh[tb + u];
            den += ev; num += ev*hv;
            float attn = __fdividef(num, den);
            __stcg(cp + (size_t)(tb + u)*HH, __float2half_rn(acc2));
            acc2 += attn;
        }
    }
}

// ---------------- host launch ----------------
extern "C" void kernel_launch(void* const* d_in, const int* in_sizes, int n_in,
                              void* d_out, int out_size){
    const int*   skill      = (const int*)  d_in[0];
    const int*   answer     = (const int*)  d_in[1];
    const float* skill_emb  = (const float*)d_in[2];
    const float* answer_emb = (const float*)d_in[3];
    const float* Wih        = (const float*)d_in[4];
    const float* Whh        = (const float*)d_in[5];
    const float* bih        = (const float*)d_in[6];
    const float* bhh        = (const float*)d_in[7];
    const float* mlp_w      = (const float*)d_in[8];
    const float* mlp_b      = (const float*)d_in[9];
    const float* sim_w      = (const float*)d_in[10];
    const float* fc_w       = (const float*)d_in[11];
    const float* fc_b       = (const float*)d_in[12];
    float* out = (float*)d_out;

    __half *p_saeh, *p_hallh, *p_cum1h, *p_wihh, *p_mlpwh, *p_fcwh;
    float  *p_xg, *p_scores;
    cudaGetSymbolAddress((void**)&p_saeh,   g_sae_h);
    cudaGetSymbolAddress((void**)&p_xg,     g_xg);
    cudaGetSymbolAddress((void**)&p_hallh,  g_hall_h);
    cudaGetSymbolAddress((void**)&p_scores, g_scores);
    cudaGetSymbolAddress((void**)&p_cum1h,  g_cum1_h);
    cudaGetSymbolAddress((void**)&p_wihh,   g_wih_h);
    cudaGetSymbolAddress((void**)&p_mlpwh,  g_mlpw_h);
    cudaGetSymbolAddress((void**)&p_fcwh,   g_fcw_h);

    cudaFuncSetAttribute(atkt_lstm_kernel,
                         cudaFuncAttributeMaxDynamicSharedMemorySize, LSTM_SMEM);
    cudaFuncSetAttribute(atkt_gemm_h,
                         cudaFuncAttributeMaxDynamicSharedMemorySize, GEMM_SMEM);

    float* out_sae = ((size_t)out_size >= RES_ELEMS + SAE_ELEMS)
                     ? (out + RES_ELEMS) : nullptr;

    // 1) embeddings -> sae_h + exact tail of output
    atkt_embed_kernel<<<BT, DD>>>(skill, answer, skill_emb, answer_emb, out_sae);
    // 2) weights -> fp16
    atkt_init_all<<<(NC*2*HH + 255)/256, 256>>>(Wih, mlp_w, fc_w);
    // 3) xg = sae @ Wih^T + bih + bhh   [32768 x 1024]
    atkt_gemm_h<<<dim3(G4/128, BT/128), 256, GEMM_SMEM>>>(
        p_saeh, DD, nullptr, 0, 0, p_wihh, bih, bhh, nullptr,
        p_xg, nullptr, BT, G4, DD, 0);
    // 4) 2-way pipelined cluster LSTM scan -> g_hall_h   (profiled slot)
    atkt_lstm_kernel<<<64, 256, LSTM_SMEM>>>(Whh);
    // 5) scores = tanh(h @ mlp_w^T + mlp_b) . sim_w   (fused)
    atkt_gemm_h<<<dim3(1, BT/128), 256, GEMM_SMEM>>>(
        p_hallh, HH, nullptr, 0, 0, p_mlpwh, mlp_b, nullptr, sim_w,
        nullptr, p_scores, BT, ATTD, HH, 3);
    // 6) causal attention cumulative ratios -> g_cum1_h
    atkt_attn_kernel<<<2*BB, 128>>>();
    // 7) res = sigmoid([cum1|h] @ fc_w^T + fc_b) -> d_out  (split-A GEMM)
    atkt_gemm_h<<<dim3((NC + 127)/128, BT/128), 256, GEMM_SMEM>>>(
        p_cum1h, HH, p_hallh, HH, 256, p_fcwh, fc_b, nullptr, nullptr,
        out, nullptr, BT, NC, 2*HH, 1);
}